// round 1
// baseline (speedup 1.0000x reference)
#include <cuda_runtime.h>
#include <math.h>

#define NN 100000
#define EE 800000
#define MAXHC 224
#define MAXH 7

// ---------------- scratch (device globals; no allocations) ----------------
__device__ float g_q[NN * MAXHC];
__device__ float g_k[NN * MAXHC];
__device__ float g_v[NN * MAXHC];
__device__ float g_h1[NN * 224];
__device__ float g_h2[NN * 128];
__device__ float g_amax[NN * MAXH];
__device__ float g_denom[NN * MAXH];
__device__ float g_alpha[EE * MAXH];

// ---------------- GEMM: Y[N,dout] = X[N,din] @ W[din,dout] + b ------------
// BM=64, BN=64, BK=32, 256 threads, 4x4 register tile per thread.
__global__ void gemm_bias_kernel(const float* __restrict__ X,
                                 const float* __restrict__ W,
                                 const float* __restrict__ bias,
                                 float* __restrict__ Y,
                                 int N, int din, int dout)
{
    __shared__ float Xs[32][68];   // [k][m], padded for 16B-aligned float4
    __shared__ float Ws[32][68];   // [k][n]

    const int tid = threadIdx.x;
    const int tx  = tid & 15;      // 0..15 -> 4 cols each
    const int ty  = tid >> 4;      // 0..15 -> 4 rows each
    const int m0  = blockIdx.x * 64;
    const int n0  = blockIdx.y * 64;

    float acc[4][4] = {};

    for (int kb = 0; kb < din; kb += 32) {
        // Load X tile (64 rows x 32 k), coalesced along k; store transposed.
        #pragma unroll
        for (int i = 0; i < 8; i++) {
            int idx = tid + i * 256;
            int r   = idx >> 5;        // 0..63
            int kk  = idx & 31;        // 0..31
            int row = m0 + r;
            Xs[kk][r] = (row < N) ? X[(size_t)row * din + kb + kk] : 0.f;
        }
        // Load W tile (32 k x 64 n), coalesced along n.
        #pragma unroll
        for (int i = 0; i < 8; i++) {
            int idx = tid + i * 256;
            int kk  = idx >> 6;        // 0..31
            int nn  = idx & 63;        // 0..63
            int cg  = n0 + nn;
            Ws[kk][nn] = (cg < dout) ? W[(size_t)(kb + kk) * dout + cg] : 0.f;
        }
        __syncthreads();

        #pragma unroll
        for (int kk = 0; kk < 32; kk++) {
            float4 xv = *(const float4*)&Xs[kk][ty * 4];
            float4 wv = *(const float4*)&Ws[kk][tx * 4];
            float xr[4] = {xv.x, xv.y, xv.z, xv.w};
            float wr[4] = {wv.x, wv.y, wv.z, wv.w};
            #pragma unroll
            for (int i = 0; i < 4; i++)
                #pragma unroll
                for (int j = 0; j < 4; j++)
                    acc[i][j] = fmaf(xr[i], wr[j], acc[i][j]);
        }
        __syncthreads();
    }

    // Epilogue: dout is always a multiple of 4, so the 4-col group is
    // all-in or all-out of range.
    int cg = n0 + tx * 4;
    if (cg + 3 < dout) {
        float4 bv = *(const float4*)&bias[cg];
        #pragma unroll
        for (int i = 0; i < 4; i++) {
            int row = m0 + ty * 4 + i;
            if (row < N) {
                float4 o;
                o.x = acc[i][0] + bv.x;
                o.y = acc[i][1] + bv.y;
                o.z = acc[i][2] + bv.z;
                o.w = acc[i][3] + bv.w;
                *(float4*)&Y[(size_t)row * dout + cg] = o;
            }
        }
    }
}

// ---------------- softmax-state init --------------------------------------
__global__ void init_softmax_kernel(float* __restrict__ amax,
                                    float* __restrict__ denom, int n)
{
    int i = blockIdx.x * blockDim.x + threadIdx.x;
    if (i < n) { amax[i] = -INFINITY; denom[i] = 0.f; }
}

// ---------------- per-edge attention logits + segment max -----------------
__global__ void edge_alpha_kernel(const float* __restrict__ q,
                                  const float* __restrict__ k,
                                  const int* __restrict__ src,
                                  const int* __restrict__ dst,
                                  float* __restrict__ alpha,
                                  float* __restrict__ amax,
                                  int E, int H, int C, float scale)
{
    int idx = blockIdx.x * blockDim.x + threadIdx.x;
    if (idx >= E * H) return;
    int e = idx / H;
    int h = idx - e * H;
    int s = src[e], d = dst[e];
    int HC = H * C;

    const float4* qp = (const float4*)(q + (size_t)d * HC + h * C);
    const float4* kp = (const float4*)(k + (size_t)s * HC + h * C);
    float acc = 0.f;
    int c4 = C >> 2;
    for (int i = 0; i < c4; i++) {
        float4 a = qp[i], b = kp[i];
        acc = fmaf(a.x, b.x, acc);
        acc = fmaf(a.y, b.y, acc);
        acc = fmaf(a.z, b.z, acc);
        acc = fmaf(a.w, b.w, acc);
    }
    acc *= scale;
    alpha[idx] = acc;

    // float atomic max via signed-max / unsigned-min trick (init = -inf)
    float* ap = &amax[d * H + h];
    if (acc >= 0.f) atomicMax((int*)ap, __float_as_int(acc));
    else            atomicMin((unsigned int*)ap, __float_as_uint(acc));
}

// ---------------- exp + segment-sum denominator ----------------------------
__global__ void edge_exp_kernel(const int* __restrict__ dst,
                                float* __restrict__ alpha,
                                const float* __restrict__ amax,
                                float* __restrict__ denom,
                                int E, int H)
{
    int idx = blockIdx.x * blockDim.x + threadIdx.x;
    if (idx >= E * H) return;
    int e = idx / H;
    int h = idx - e * H;
    int d = dst[e];
    float ex = expf(alpha[idx] - amax[d * H + h]);
    alpha[idx] = ex;
    atomicAdd(&denom[d * H + h], ex);
}

// ---------------- weighted message scatter ---------------------------------
__global__ void edge_agg_kernel(const float* __restrict__ v,
                                const int* __restrict__ src,
                                const int* __restrict__ dst,
                                const float* __restrict__ alpha,
                                const float* __restrict__ denom,
                                float* __restrict__ out,
                                int E, int H, int C)
{
    int idx = blockIdx.x * blockDim.x + threadIdx.x;
    if (idx >= E * H) return;
    int e = idx / H;
    int h = idx - e * H;
    int s = src[e], d = dst[e];
    int HC = H * C;

    float attn = alpha[idx] / (denom[d * H + h] + 1e-16f);
    const float4* vp = (const float4*)(v + (size_t)s * HC + h * C);
    float* op = out + (size_t)d * HC + h * C;
    int c4 = C >> 2;
    for (int i = 0; i < c4; i++) {
        float4 m = vp[i];
        atomicAdd(&op[4 * i + 0], m.x * attn);
        atomicAdd(&op[4 * i + 1], m.y * attn);
        atomicAdd(&op[4 * i + 2], m.z * attn);
        atomicAdd(&op[4 * i + 3], m.w * attn);
    }
}

// ---------------- relu -----------------------------------------------------
__global__ void relu_kernel(float* __restrict__ x, int n)
{
    int i = blockIdx.x * blockDim.x + threadIdx.x;
    if (i < n) x[i] = fmaxf(x[i], 0.f);
}

// ---------------- host-side orchestration ----------------------------------
static float* sym_addr(const void* symbol)
{
    void* p = nullptr;
    cudaGetSymbolAddress(&p, symbol);
    return (float*)p;
}

static void run_layer(const float* xin, int din, int H, int C,
                      const float* Wq, const float* bq,
                      const float* Wk, const float* bk,
                      const float* Wv, const float* bv,
                      const float* Ws, const float* bs,
                      float* out,
                      const int* src, const int* dst, int E,
                      float* q, float* k, float* v,
                      float* amax, float* denom, float* alpha,
                      bool relu)
{
    const int N = NN;
    const int HC = H * C;
    dim3 ggrid((N + 63) / 64, (HC + 63) / 64);

    gemm_bias_kernel<<<ggrid, 256>>>(xin, Wq, bq, q,   N, din, HC);
    gemm_bias_kernel<<<ggrid, 256>>>(xin, Wk, bk, k,   N, din, HC);
    gemm_bias_kernel<<<ggrid, 256>>>(xin, Wv, bv, v,   N, din, HC);
    gemm_bias_kernel<<<ggrid, 256>>>(xin, Ws, bs, out, N, din, HC);  // skip init

    int nh = N * H;
    init_softmax_kernel<<<(nh + 255) / 256, 256>>>(amax, denom, nh);

    int eh = E * H;
    int eb = (eh + 255) / 256;
    float scale = 1.0f / sqrtf((float)C);
    edge_alpha_kernel<<<eb, 256>>>(q, k, src, dst, alpha, amax, E, H, C, scale);
    edge_exp_kernel<<<eb, 256>>>(dst, alpha, amax, denom, E, H);
    edge_agg_kernel<<<eb, 256>>>(v, src, dst, alpha, denom, out, E, H, C);

    if (relu) {
        int n = N * HC;
        relu_kernel<<<(n + 255) / 256, 256>>>(out, n);
    }
}

extern "C" void kernel_launch(void* const* d_in, const int* in_sizes, int n_in,
                              void* d_out, int out_size)
{
    const float* x  = (const float*)d_in[0];
    const int*   ei = (const int*)d_in[1];
    const int E = in_sizes[1] / 2;
    const int* src = ei;
    const int* dst = ei + E;

    const float* W[24];
    for (int i = 0; i < 24; i++) W[i] = (const float*)d_in[2 + i];

    float* q     = sym_addr(g_q);
    float* k     = sym_addr(g_k);
    float* v     = sym_addr(g_v);
    float* h1    = sym_addr(g_h1);
    float* h2    = sym_addr(g_h2);
    float* amax  = sym_addr(g_amax);
    float* denom = sym_addr(g_denom);
    float* alpha = sym_addr(g_alpha);
    float* out   = (float*)d_out;

    // Layer 1: din=64,  H=7, C=32, relu
    run_layer(x,  64, 7, 32, W[0], W[1], W[2], W[3], W[4], W[5], W[6], W[7],
              h1, src, dst, E, q, k, v, amax, denom, alpha, true);
    // Layer 2: din=224, H=4, C=32, relu
    run_layer(h1, 224, 4, 32, W[8], W[9], W[10], W[11], W[12], W[13], W[14], W[15],
              h2, src, dst, E, q, k, v, amax, denom, alpha, true);
    // Layer 3: din=128, H=1, C=64, no relu -> d_out
    run_layer(h2, 128, 1, 64, W[16], W[17], W[18], W[19], W[20], W[21], W[22], W[23],
              out, src, dst, E, q, k, v, amax, denom, alpha, false);
}

// round 2
// speedup vs baseline: 1.9671x; 1.9671x over previous
#include <cuda_runtime.h>
#include <math.h>

#define NN 100000
#define EE 800000
#define MAXHC 224

// ---------------- scratch (device globals; no allocations) ----------------
__device__ float g_q[NN * MAXHC];
__device__ float g_k[NN * MAXHC];
__device__ float g_v[NN * MAXHC];
__device__ float g_h1[NN * 224];
__device__ float g_h2[NN * 128];
// CSR scratch
__device__ int g_cnt[NN];
__device__ int g_row[NN + 1];
__device__ int g_cur[NN];
__device__ int g_bsum[256];
__device__ int g_boff[256];
__device__ int g_csrc[EE];

// =====================================================================
// GEMM: Y[N,dout] = X[N,din] @ W[din,dout] + b
// BM=128, BN=16*TN, BK=16, 256 threads, 8 x TN register tile.
// din must be a multiple of 16 (64/224/128 ok), dout a multiple of TN.
// =====================================================================
template <int TN>
__global__ void __launch_bounds__(256, 2)
gemm_bias(const float* __restrict__ X, const float* __restrict__ W,
          const float* __restrict__ bias, float* __restrict__ Y,
          int N, int din, int dout)
{
    constexpr int BN = 16 * TN;
    __shared__ float Xs[16][132];       // [k][m]
    __shared__ float Ws[16][BN + 4];    // [k][n]

    const int tid = threadIdx.x;
    const int tx  = tid & 15;
    const int ty  = tid >> 4;
    const int m0  = blockIdx.x * 128;
    const int n0  = blockIdx.y * BN;

    float acc[8][TN] = {};

    for (int kb = 0; kb < din; kb += 16) {
        // --- load X tile (128 rows x 16 k), float4 along k, store transposed
        #pragma unroll
        for (int it = 0; it < 2; it++) {
            int r   = tid >> 1;                      // 0..127
            int kk4 = ((tid & 1) * 2 + it) * 4;      // 0,4,8,12
            int row = m0 + r;
            float4 xv = make_float4(0.f, 0.f, 0.f, 0.f);
            if (row < N)
                xv = *(const float4*)&X[(size_t)row * din + kb + kk4];
            Xs[kk4 + 0][r] = xv.x;
            Xs[kk4 + 1][r] = xv.y;
            Xs[kk4 + 2][r] = xv.z;
            Xs[kk4 + 3][r] = xv.w;
        }
        // --- load W tile (16 k x BN n), float4 along n
        #pragma unroll
        for (int it = 0; it < BN / 64; it++) {
            int kk = tid >> 4;                                // 0..15
            int nn = ((tid & 15) * (BN / 64) + it) * 4;       // 0..BN-4
            int col = n0 + nn;
            float4 wv = make_float4(0.f, 0.f, 0.f, 0.f);
            if (col < dout)                                   // dout mult of 4
                wv = *(const float4*)&W[(size_t)(kb + kk) * dout + col];
            *(float4*)&Ws[kk][nn] = wv;
        }
        __syncthreads();

        #pragma unroll
        for (int kk = 0; kk < 16; kk++) {
            float a[8], b[TN];
            *(float4*)&a[0] = *(const float4*)&Xs[kk][ty * 8];
            *(float4*)&a[4] = *(const float4*)&Xs[kk][ty * 8 + 4];
            #pragma unroll
            for (int jj = 0; jj < TN; jj += 4)
                *(float4*)&b[jj] = *(const float4*)&Ws[kk][tx * TN + jj];
            #pragma unroll
            for (int i = 0; i < 8; i++)
                #pragma unroll
                for (int j = 0; j < TN; j++)
                    acc[i][j] = fmaf(a[i], b[j], acc[i][j]);
        }
        __syncthreads();
    }

    // --- epilogue (dout is a multiple of TN, so group all-in or all-out)
    int cg = n0 + tx * TN;
    if (cg < dout) {
        float bv[TN];
        #pragma unroll
        for (int jj = 0; jj < TN; jj += 4)
            *(float4*)&bv[jj] = *(const float4*)&bias[cg + jj];
        #pragma unroll
        for (int i = 0; i < 8; i++) {
            int row = m0 + ty * 8 + i;
            if (row < N) {
                #pragma unroll
                for (int jj = 0; jj < TN; jj += 4) {
                    float4 o;
                    o.x = acc[i][jj + 0] + bv[jj + 0];
                    o.y = acc[i][jj + 1] + bv[jj + 1];
                    o.z = acc[i][jj + 2] + bv[jj + 2];
                    o.w = acc[i][jj + 3] + bv[jj + 3];
                    *(float4*)&Y[(size_t)row * dout + cg + jj] = o;
                }
            }
        }
    }
}

// =====================================================================
// CSR build: histogram by dst -> exclusive scan -> scatter edge srcs
// =====================================================================
__global__ void zero_cnt_kernel(int* __restrict__ cnt, int n)
{
    int i = blockIdx.x * blockDim.x + threadIdx.x;
    if (i < n) cnt[i] = 0;
}

__global__ void hist_kernel(const int* __restrict__ dst, int* __restrict__ cnt, int E)
{
    int e = blockIdx.x * blockDim.x + threadIdx.x;
    if (e < E) atomicAdd(&cnt[dst[e]], 1);
}

__global__ void scan_block_kernel(const int* __restrict__ cnt,
                                  int* __restrict__ row,
                                  int* __restrict__ bsum, int n)
{
    __shared__ int sh[512];
    int t = threadIdx.x;
    int g = blockIdx.x * 512 + t;
    int v = (g < n) ? cnt[g] : 0;
    sh[t] = v;
    __syncthreads();
    #pragma unroll
    for (int off = 1; off < 512; off <<= 1) {
        int tmp = (t >= off) ? sh[t - off] : 0;
        __syncthreads();
        sh[t] += tmp;
        __syncthreads();
    }
    if (g < n) row[g] = sh[t] - v;   // exclusive
    if (t == 511) bsum[blockIdx.x] = sh[511];
}

__global__ void scan_bsum_kernel(const int* __restrict__ bsum,
                                 int* __restrict__ boff, int nb)
{
    __shared__ int sh[256];
    int t = threadIdx.x;
    int v = (t < nb) ? bsum[t] : 0;
    sh[t] = v;
    __syncthreads();
    #pragma unroll
    for (int off = 1; off < 256; off <<= 1) {
        int tmp = (t >= off) ? sh[t - off] : 0;
        __syncthreads();
        sh[t] += tmp;
        __syncthreads();
    }
    boff[t] = sh[t] - v;   // exclusive
}

__global__ void scan_add_kernel(int* __restrict__ row, const int* __restrict__ boff,
                                int* __restrict__ cur, int n)
{
    int g = blockIdx.x * blockDim.x + threadIdx.x;
    if (g < n) {
        int r = row[g] + boff[g >> 9];
        row[g] = r;
        cur[g] = r;
    }
}

__global__ void scatter_kernel(const int* __restrict__ src, const int* __restrict__ dst,
                               int* __restrict__ cur, int* __restrict__ csrc, int E)
{
    int e = blockIdx.x * blockDim.x + threadIdx.x;
    if (e < E) {
        int p = atomicAdd(&cur[dst[e]], 1);
        csrc[p] = src[e];
    }
}

// =====================================================================
// Attention: one warp per (dst node, head), online softmax over CSR edges.
// C = 32*VPT. Adds result to `out` (which holds the skip projection).
// =====================================================================
template <int VPT>
__global__ void attn_kernel(const float* __restrict__ q,
                            const float* __restrict__ k,
                            const float* __restrict__ v,
                            const int* __restrict__ row,
                            const int* __restrict__ cnt,
                            const int* __restrict__ csrc,
                            float* __restrict__ out,
                            int H, float scale, int relu, int NHtot)
{
    int w    = (blockIdx.x * blockDim.x + threadIdx.x) >> 5;
    int lane = threadIdx.x & 31;
    if (w >= NHtot) return;
    int n = w / H;
    int h = w - n * H;
    const int C  = VPT * 32;
    const int HC = H * C;
    int base_off = n * HC + h * C;

    float qv[VPT];
    #pragma unroll
    for (int j = 0; j < VPT; j++) qv[j] = q[base_off + j * 32 + lane];

    int start = row[n];
    int deg   = cnt[n];

    float m = -INFINITY, l = 0.f;
    float acc[VPT];
    #pragma unroll
    for (int j = 0; j < VPT; j++) acc[j] = 0.f;

    for (int base = 0; base < deg; base += 32) {
        int nb = min(32, deg - base);
        int s_lane = (lane < nb) ? csrc[start + base + lane] : 0;
        for (int i = 0; i < nb; i++) {
            int s = __shfl_sync(0xffffffffu, s_lane, i);
            int koff = s * HC + h * C;
            float dot = 0.f;
            float kv[VPT], vv[VPT];
            #pragma unroll
            for (int j = 0; j < VPT; j++) {
                kv[j] = __ldg(&k[koff + j * 32 + lane]);
                vv[j] = __ldg(&v[koff + j * 32 + lane]);
                dot = fmaf(qv[j], kv[j], dot);
            }
            #pragma unroll
            for (int off = 16; off; off >>= 1)
                dot += __shfl_xor_sync(0xffffffffu, dot, off);
            dot *= scale;

            float mn   = fmaxf(m, dot);
            float corr = __expf(m - mn);
            float p    = __expf(dot - mn);
            l = l * corr + p;
            #pragma unroll
            for (int j = 0; j < VPT; j++)
                acc[j] = acc[j] * corr + p * vv[j];
            m = mn;
        }
    }

    float inv = 1.0f / (l + 1e-16f);
    #pragma unroll
    for (int j = 0; j < VPT; j++) {
        float o = out[base_off + j * 32 + lane] + acc[j] * inv;
        if (relu) o = fmaxf(o, 0.f);
        out[base_off + j * 32 + lane] = o;
    }
}

// =====================================================================
// Host-side orchestration
// =====================================================================
static float* sym_addr_f(const void* symbol)
{
    void* p = nullptr;
    cudaGetSymbolAddress(&p, symbol);
    return (float*)p;
}
static int* sym_addr_i(const void* symbol)
{
    void* p = nullptr;
    cudaGetSymbolAddress(&p, symbol);
    return (int*)p;
}

static void launch_gemm(const float* X, const float* W, const float* b, float* Y,
                        int N, int din, int dout)
{
    if (dout >= 128) {
        dim3 grid((N + 127) / 128, (dout + 127) / 128);
        gemm_bias<8><<<grid, 256>>>(X, W, b, Y, N, din, dout);
    } else {
        dim3 grid((N + 127) / 128, (dout + 63) / 64);
        gemm_bias<4><<<grid, 256>>>(X, W, b, Y, N, din, dout);
    }
}

static void run_layer(const float* xin, int din, int H, int C,
                      const float* const* W, float* out,
                      int N, int E,
                      float* q, float* k, float* v,
                      const int* row, const int* cnt, const int* csrc,
                      bool relu)
{
    const int HC = H * C;
    launch_gemm(xin, W[0], W[1], q,   N, din, HC);
    launch_gemm(xin, W[2], W[3], k,   N, din, HC);
    launch_gemm(xin, W[4], W[5], v,   N, din, HC);
    launch_gemm(xin, W[6], W[7], out, N, din, HC);   // skip -> out

    int NH = N * H;
    int blocks = (NH * 32 + 255) / 256;
    float scale = 1.0f / sqrtf((float)C);
    if (C == 32)
        attn_kernel<1><<<blocks, 256>>>(q, k, v, row, cnt, csrc, out, H, scale, relu ? 1 : 0, NH);
    else
        attn_kernel<2><<<blocks, 256>>>(q, k, v, row, cnt, csrc, out, H, scale, relu ? 1 : 0, NH);
}

extern "C" void kernel_launch(void* const* d_in, const int* in_sizes, int n_in,
                              void* d_out, int out_size)
{
    const float* x  = (const float*)d_in[0];
    const int*   ei = (const int*)d_in[1];
    const int N = in_sizes[0] / 64;
    const int E = in_sizes[1] / 2;
    const int* src = ei;
    const int* dst = ei + E;

    const float* W[24];
    for (int i = 0; i < 24; i++) W[i] = (const float*)d_in[2 + i];

    float* q    = sym_addr_f(g_q);
    float* k    = sym_addr_f(g_k);
    float* v    = sym_addr_f(g_v);
    float* h1   = sym_addr_f(g_h1);
    float* h2   = sym_addr_f(g_h2);
    int*   cnt  = sym_addr_i(g_cnt);
    int*   row  = sym_addr_i(g_row);
    int*   cur  = sym_addr_i(g_cur);
    int*   bsum = sym_addr_i(g_bsum);
    int*   boff = sym_addr_i(g_boff);
    int*   csrc = sym_addr_i(g_csrc);
    float* out  = (float*)d_out;

    // ---- CSR build (once; reused by all 3 layers) ----
    int nscan = (N + 511) / 512;   // 196 blocks (<= 256)
    zero_cnt_kernel<<<(N + 255) / 256, 256>>>(cnt, N);
    hist_kernel<<<(E + 255) / 256, 256>>>(dst, cnt, E);
    scan_block_kernel<<<nscan, 512>>>(cnt, row, bsum, N);
    scan_bsum_kernel<<<1, 256>>>(bsum, boff, nscan);
    scan_add_kernel<<<(N + 255) / 256, 256>>>(row, boff, cur, N);
    scatter_kernel<<<(E + 255) / 256, 256>>>(src, dst, cur, csrc, E);

    // ---- layers ----
    run_layer(x,  64,  7, 32, W + 0,  h1,  N, E, q, k, v, row, cnt, csrc, true);
    run_layer(h1, 224, 4, 32, W + 8,  h2,  N, E, q, k, v, row, cnt, csrc, true);
    run_layer(h2, 128, 1, 64, W + 16, out, N, E, q, k, v, row, cnt, csrc, false);
}